// round 12
// baseline (speedup 1.0000x reference)
#include <cuda_runtime.h>

// Hausdorff distance, batched N=8, grid 96x96, coords (i/96, j/96).
// haus[s] = max(directed(A\B -> B), directed(B\A -> A)), out = mean over s.
// Single fused pass: warp w owns rows 3w..3w+2, lane owns j = lane,+32,+64.
// Row masks in-register via ballot; rd2 via 32-bit centered window (funnelshift
// + clz/ffs) with exact 64-bit fallback for empty half-windows; one barrier;
// column scan: branchless di=1 probe + early-exit loop.

#define HD 96
#define WD 96
#define HW (HD * WD)
#define NT 1024

__device__ float        g_dir[64];     // [s*2 + dir]
__device__ unsigned int g_count = 0;   // self-resetting last-block counter

// Exact left/right nearest-set-bit distance in a 96-bit row (cold path).
static __device__ int exact_dl(int j, unsigned m0, unsigned m1, unsigned m2) {
    unsigned long long lo = (unsigned long long)m0 | ((unsigned long long)m1 << 32);
    if (j < 64) {
        unsigned long long x = lo & (~0ULL >> (63 - j));
        return x ? (j - (63 - __clzll(x))) : 200;
    } else {
        unsigned x = m2 & (~0u >> (95 - j));
        if (x)  return j - (64 + 31 - __clz(x));
        if (lo) return j - (63 - __clzll(lo));
        return 200;
    }
}
static __device__ int exact_dr(int j, unsigned m0, unsigned m1, unsigned m2) {
    unsigned long long lo = (unsigned long long)m0 | ((unsigned long long)m1 << 32);
    if (j < 64) {
        unsigned long long y = lo >> j;
        if (y)  return __ffsll(y) - 1;
        if (m2) return (64 - j) + __ffs(m2) - 1;
        return 200;
    } else {
        unsigned y = m2 >> (j - 64);
        return y ? (__ffs(y) - 1) : 200;
    }
}

__global__ void __launch_bounds__(NT) hausdorff_kernel(
    const float* __restrict__ pred, const float* __restrict__ targ,
    float* __restrict__ out, int n) {
    __shared__ unsigned short s_rd2[HW];   // squared row distance (sentinel 40000)
    __shared__ int s_red[32];

    const int s    = blockIdx.x;
    const int dir  = blockIdx.y;           // 0: tgt=B, src=A&~B ; 1: tgt=A, src=B&~A
    const int tid  = threadIdx.x;
    const int lane = tid & 31;
    const int wrp  = tid >> 5;             // 0..31 -> rows 3w..3w+2

    const float* __restrict__ P = pred + s * HW;
    const float* __restrict__ T = targ + s * HW;

    // ---- Load this warp's 3 rows (both arrays), 18 coalesced scalar loads.
    float av[9], bv[9];
    #pragma unroll
    for (int rr = 0; rr < 3; rr++) {
        const int base = (wrp * 3 + rr) * WD + lane;
        #pragma unroll
        for (int c = 0; c < 3; c++) {
            av[rr * 3 + c] = P[base + 32 * c];
            bv[rr * 3 + c] = T[base + 32 * c];
        }
    }

    // ---- Build row masks via ballot; rd2 from 32-bit centered windows.
    unsigned srcbits = 0;            // bit rr*3+c: this lane's pixel is a source
    unsigned anyT = 0;
    int rd2own[9];
    const bool loHalf = (lane < 16);
    #pragma unroll
    for (int rr = 0; rr < 3; rr++) {
        unsigned tm[3];
        #pragma unroll
        for (int c = 0; c < 3; c++) {
            bool a = av[rr * 3 + c] > 0.5f;   // round(x)>0.5 <=> x>0.5 on [0,1)
            bool b = bv[rr * 3 + c] > 0.5f;
            unsigned am = __ballot_sync(0xffffffffu, a);
            unsigned bm = __ballot_sync(0xffffffffu, b);
            tm[c] = dir ? am : bm;
            bool src = dir ? (b && !a) : (a && !b);
            srcbits |= (unsigned)src << (rr * 3 + c);
        }
        anyT |= tm[0] | tm[1] | tm[2];
        const int i = wrp * 3 + rr;

        #pragma unroll
        for (int c = 0; c < 3; c++) {
            const int j = lane + 32 * c;
            const unsigned mprev = (c == 0) ? 0u : tm[c - 1];
            const unsigned mcur  = tm[c];
            const unsigned mnext = (c == 2) ? 0u : tm[c + 1];
            // 32-bit window: bit k <-> row position j-16+k
            unsigned w = loHalf ? __funnelshift_r(mprev, mcur, lane + 16)
                                : __funnelshift_r(mcur, mnext, lane - 16);
            unsigned x = w & 0x1FFFFu;     // positions j-16..j
            unsigned y = w >> 16;          // positions j..j+15
            int dl = x ? (__clz(x) - 15) : exact_dl(j, tm[0], tm[1], tm[2]);
            int dr = y ? (__ffs(y) - 1)  : exact_dr(j, tm[0], tm[1], tm[2]);
            int v = min(dl, dr);
            int v2 = v * v;
            rd2own[rr * 3 + c] = v2;
            s_rd2[i * WD + j] = (unsigned short)v2;
        }
    }

    // Single barrier: global anyTgt OR + makes s_rd2 visible block-wide.
    const int anyTgt = __syncthreads_or((int)(anyT != 0));

    // ---- Column scan: branchless di=1 probe + early-exit loop from di=2.
    // Clamped boundary probes only duplicate candidates already covered => min safe.
    int best = -1;
    #pragma unroll
    for (int rr = 0; rr < 3; rr++) {
        const int i = wrp * 3 + rr;
        #pragma unroll
        for (int c = 0; c < 3; c++) {
            const int j = lane + 32 * c;
            int bst = ((srcbits >> (rr * 3 + c)) & 1u) ? rd2own[rr * 3 + c] : -1;
            const int loA = j;                 // row 0 clamp
            const int hiA = 95 * WD + j;       // row 95 clamp
            int au  = max(i * WD + j - WD, loA);
            int avd = min(i * WD + j + WD, hiA);
            bst = min(bst, 1 + (int)s_rd2[au]);
            bst = min(bst, 1 + (int)s_rd2[avd]);
            int di = 2, d2 = 4;
            while (d2 < bst) {                 // rare: only when local rd2 > 4
                au  = max(au - WD, loA);
                avd = min(avd + WD, hiA);
                bst = min(bst, d2 + (int)s_rd2[au]);
                bst = min(bst, d2 + (int)s_rd2[avd]);
                d2 += 2 * di + 1;
                di++;
            }
            best = max(best, bst);
        }
    }

    // ---- Block max-reduction
    #pragma unroll
    for (int off = 16; off > 0; off >>= 1)
        best = max(best, __shfl_xor_sync(0xffffffffu, best, off));
    if (lane == 0) s_red[wrp] = best;
    __syncthreads();
    if (wrp == 0) {
        int m = s_red[lane];
        #pragma unroll
        for (int off = 16; off > 0; off >>= 1)
            m = max(m, __shfl_xor_sync(0xffffffffu, m, off));
        if (lane == 0) {
            float r;
            if (m < 0)        r = 0.0f;                  // empty source set
            else if (!anyTgt) r = 1e9f;                  // src nonempty, tgt empty
            else              r = sqrtf((float)m) * (1.0f / 96.0f);
            g_dir[s * 2 + dir] = r;
            __threadfence();
            unsigned int t = atomicAdd(&g_count, 1);
            if (t == (unsigned int)(2 * n - 1)) {        // last block: finish + reset
                __threadfence();
                volatile float* gd = g_dir;
                float acc = 0.0f;
                for (int i = 0; i < n; i++)
                    acc += fmaxf(gd[2 * i], gd[2 * i + 1]);
                out[0] = acc / (float)n;
                g_count = 0;                             // self-reset for next replay
            }
        }
    }
}

extern "C" void kernel_launch(void* const* d_in, const int* in_sizes, int n_in,
                              void* d_out, int out_size) {
    const float* pred = (const float*)d_in[0];
    const float* targ = (const float*)d_in[1];
    float* out = (float*)d_out;
    int n = in_sizes[0] / HW;   // batch size (8)

    dim3 grid(n, 2);
    hausdorff_kernel<<<grid, NT>>>(pred, targ, out, n);
}

// round 13
// speedup vs baseline: 1.3895x; 1.3895x over previous
#include <cuda_runtime.h>

// Hausdorff distance, batched N=8, grid 96x96, coords (i/96, j/96).
// haus[s] = max(directed(A\B -> B), directed(B\A -> A)), out = mean over s.
// Single fused pass: warp w owns rows 3w..3w+2, lane owns j = lane,+32,+64.
// Target row masks via 9 ballots (src bits stay per-lane); rd2 via 32-bit
// centered window (funnelshift + clz/ffs) with exact 64-bit fallback;
// one barrier; column scan: two batched branchless probe levels (MLP) + rare tail.

#define HD 96
#define WD 96
#define HW (HD * WD)
#define NT 1024

__device__ float        g_dir[64];     // [s*2 + dir]
__device__ unsigned int g_count = 0;   // self-resetting last-block counter

// Exact left/right nearest-set-bit distance in a 96-bit row (cold path).
static __device__ int exact_dl(int j, unsigned m0, unsigned m1, unsigned m2) {
    unsigned long long lo = (unsigned long long)m0 | ((unsigned long long)m1 << 32);
    if (j < 64) {
        unsigned long long x = lo & (~0ULL >> (63 - j));
        return x ? (j - (63 - __clzll(x))) : 200;
    } else {
        unsigned x = m2 & (~0u >> (95 - j));
        if (x)  return j - (64 + 31 - __clz(x));
        if (lo) return j - (63 - __clzll(lo));
        return 200;
    }
}
static __device__ int exact_dr(int j, unsigned m0, unsigned m1, unsigned m2) {
    unsigned long long lo = (unsigned long long)m0 | ((unsigned long long)m1 << 32);
    if (j < 64) {
        unsigned long long y = lo >> j;
        if (y)  return __ffsll(y) - 1;
        if (m2) return (64 - j) + __ffs(m2) - 1;
        return 200;
    } else {
        unsigned y = m2 >> (j - 64);
        return y ? (__ffs(y) - 1) : 200;
    }
}

__global__ void __launch_bounds__(NT) hausdorff_kernel(
    const float* __restrict__ pred, const float* __restrict__ targ,
    float* __restrict__ out, int n) {
    __shared__ unsigned short s_rd2[HW];   // squared row distance (sentinel 40000)
    __shared__ int s_red[32];

    const int s    = blockIdx.x;
    const int dir  = blockIdx.y;           // 0: tgt=B, src=A&~B ; 1: tgt=A, src=B&~A
    const int tid  = threadIdx.x;
    const int lane = tid & 31;
    const int wrp  = tid >> 5;             // 0..31 -> rows 3w..3w+2

    const float* __restrict__ P = pred + s * HW;
    const float* __restrict__ T = targ + s * HW;

    // ---- Load this warp's 3 rows (both arrays), 18 coalesced scalar loads.
    float av[9], bv[9];
    #pragma unroll
    for (int rr = 0; rr < 3; rr++) {
        const int base = (wrp * 3 + rr) * WD + lane;
        #pragma unroll
        for (int c = 0; c < 3; c++) {
            av[rr * 3 + c] = P[base + 32 * c];
            bv[rr * 3 + c] = T[base + 32 * c];
        }
    }

    // ---- Target masks via 9 ballots; source bits per-lane (no ballot).
    unsigned srcbits = 0;            // bit rr*3+c: this lane's pixel is a source
    unsigned anyT = 0;
    int rd2own[9];
    const bool loHalf = (lane < 16);
    #pragma unroll
    for (int rr = 0; rr < 3; rr++) {
        unsigned tm[3];
        #pragma unroll
        for (int c = 0; c < 3; c++) {
            bool a = av[rr * 3 + c] > 0.5f;   // round(x)>0.5 <=> x>0.5 on [0,1)
            bool b = bv[rr * 3 + c] > 0.5f;
            bool tgt = dir ? a : b;
            bool src = dir ? (b && !a) : (a && !b);
            tm[c] = __ballot_sync(0xffffffffu, tgt);
            srcbits |= (unsigned)src << (rr * 3 + c);
        }
        anyT |= tm[0] | tm[1] | tm[2];
        const int i = wrp * 3 + rr;

        #pragma unroll
        for (int c = 0; c < 3; c++) {
            const int j = lane + 32 * c;
            const unsigned mprev = (c == 0) ? 0u : tm[c - 1];
            const unsigned mcur  = tm[c];
            const unsigned mnext = (c == 2) ? 0u : tm[c + 1];
            // 32-bit window: bit k <-> row position j-16+k
            unsigned w = loHalf ? __funnelshift_r(mprev, mcur, lane + 16)
                                : __funnelshift_r(mcur, mnext, lane - 16);
            unsigned x = w & 0x1FFFFu;     // positions j-16..j
            unsigned y = w >> 16;          // positions j..j+15
            int dl = x ? (__clz(x) - 15) : exact_dl(j, tm[0], tm[1], tm[2]);
            int dr = y ? (__ffs(y) - 1)  : exact_dr(j, tm[0], tm[1], tm[2]);
            int v = min(dl, dr);
            int v2 = v * v;
            rd2own[rr * 3 + c] = v2;
            s_rd2[i * WD + j] = (unsigned short)v2;
        }
    }

    // Single barrier: global anyTgt OR + makes s_rd2 visible block-wide.
    const int anyTgt = __syncthreads_or((int)(anyT != 0));

    // ---- Column scan. Two batched branchless probe levels (high MLP), then
    // a rare per-pixel early-exit tail from di=3. Clamped boundary probes only
    // duplicate candidates already covered exactly => min unchanged.
    int bst[9];
    int au[9], avd[9];
    #pragma unroll
    for (int rr = 0; rr < 3; rr++) {
        #pragma unroll
        for (int c = 0; c < 3; c++) {
            const int idx = rr * 3 + c;
            const int i = wrp * 3 + rr;
            const int j = lane + 32 * c;
            bst[idx] = ((srcbits >> idx) & 1u) ? rd2own[idx] : -1;
            au[idx]  = max(i - 1, 0) * WD + j;
            avd[idx] = min(i + 1, HD - 1) * WD + j;
        }
    }
    // level di=1: batch all 18 LDS, then fold
    {
        int tu[9], tv[9];
        #pragma unroll
        for (int idx = 0; idx < 9; idx++) {
            tu[idx] = s_rd2[au[idx]];
            tv[idx] = s_rd2[avd[idx]];
        }
        #pragma unroll
        for (int idx = 0; idx < 9; idx++)
            bst[idx] = min(bst[idx], 1 + min(tu[idx], tv[idx]));
    }
    // level di=2: batch again (clamped address step)
    {
        const int j0 = lane;
        int tu[9], tv[9];
        #pragma unroll
        for (int idx = 0; idx < 9; idx++) {
            const int j = j0 + 32 * (idx % 3);
            au[idx]  = max(au[idx] - WD, j);
            avd[idx] = min(avd[idx] + WD, 95 * WD + j);
            tu[idx] = s_rd2[au[idx]];
            tv[idx] = s_rd2[avd[idx]];
        }
        #pragma unroll
        for (int idx = 0; idx < 9; idx++)
            bst[idx] = min(bst[idx], 4 + min(tu[idx], tv[idx]));
    }
    // rare tail from di=3 (only when local neighborhood is distant)
    int best = -1;
    #pragma unroll
    for (int idx = 0; idx < 9; idx++) {
        int b = bst[idx];
        if (b > 9) {
            const int j = lane + 32 * (idx % 3);
            int u = au[idx], v = avd[idx];
            int di = 3, d2 = 9;
            do {
                u = max(u - WD, j);
                v = min(v + WD, 95 * WD + j);
                b = min(b, d2 + (int)s_rd2[u]);
                b = min(b, d2 + (int)s_rd2[v]);
                d2 += 2 * di + 1;
                di++;
            } while (d2 < b);
        }
        best = max(best, b);
    }

    // ---- Block max-reduction (REDUX within warps)
    best = __reduce_max_sync(0xffffffffu, best);
    if (lane == 0) s_red[wrp] = best;
    __syncthreads();
    if (wrp == 0) {
        int m = __reduce_max_sync(0xffffffffu, s_red[lane]);
        if (lane == 0) {
            float r;
            if (m < 0)        r = 0.0f;                  // empty source set
            else if (!anyTgt) r = 1e9f;                  // src nonempty, tgt empty
            else              r = sqrtf((float)m) * (1.0f / 96.0f);
            g_dir[s * 2 + dir] = r;
            __threadfence();
            unsigned int t = atomicAdd(&g_count, 1);
            if (t == (unsigned int)(2 * n - 1)) {        // last block: finish + reset
                __threadfence();
                volatile float* gd = g_dir;
                float acc = 0.0f;
                for (int i = 0; i < n; i++)
                    acc += fmaxf(gd[2 * i], gd[2 * i + 1]);
                out[0] = acc / (float)n;
                g_count = 0;                             // self-reset for next replay
            }
        }
    }
}

extern "C" void kernel_launch(void* const* d_in, const int* in_sizes, int n_in,
                              void* d_out, int out_size) {
    const float* pred = (const float*)d_in[0];
    const float* targ = (const float*)d_in[1];
    float* out = (float*)d_out;
    int n = in_sizes[0] / HW;   // batch size (8)

    dim3 grid(n, 2);
    hausdorff_kernel<<<grid, NT>>>(pred, targ, out, n);
}

// round 14
// speedup vs baseline: 1.4618x; 1.0520x over previous
#include <cuda_runtime.h>

// Hausdorff distance, batched N=8, grid 96x96, coords (i/96, j/96).
// haus[s] = max(directed(A\B -> B), directed(B\A -> A)), out = mean over s.
// Single fused pass: warp w owns rows 3w..3w+2, lane owns j = lane,+32,+64.
// Target row masks via 9 ballots; rd2 via 32-bit centered window (funnelshift
// + clz/ffs); exact 96-bit fallback behind a warp-voted cold branch;
// one barrier; column scan: branchless di=1 probe + early-exit loop from di=2.

#define HD 96
#define WD 96
#define HW (HD * WD)
#define NT 1024

__device__ float        g_dir[64];     // [s*2 + dir]
__device__ unsigned int g_count = 0;   // self-resetting last-block counter

// Exact left/right nearest-set-bit distance in a 96-bit row (cold path only).
static __device__ __noinline__ int exact_dl(int j, unsigned m0, unsigned m1, unsigned m2) {
    unsigned long long lo = (unsigned long long)m0 | ((unsigned long long)m1 << 32);
    if (j < 64) {
        unsigned long long x = lo & (~0ULL >> (63 - j));
        return x ? (j - (63 - __clzll(x))) : 200;
    } else {
        unsigned x = m2 & (~0u >> (95 - j));
        if (x)  return j - (64 + 31 - __clz(x));
        if (lo) return j - (63 - __clzll(lo));
        return 200;
    }
}
static __device__ __noinline__ int exact_dr(int j, unsigned m0, unsigned m1, unsigned m2) {
    unsigned long long lo = (unsigned long long)m0 | ((unsigned long long)m1 << 32);
    if (j < 64) {
        unsigned long long y = lo >> j;
        if (y)  return __ffsll(y) - 1;
        if (m2) return (64 - j) + __ffs(m2) - 1;
        return 200;
    } else {
        unsigned y = m2 >> (j - 64);
        return y ? (__ffs(y) - 1) : 200;
    }
}

__global__ void __launch_bounds__(NT) hausdorff_kernel(
    const float* __restrict__ pred, const float* __restrict__ targ,
    float* __restrict__ out, int n) {
    __shared__ unsigned short s_rd2[HW];   // squared row distance (sentinel 40000)
    __shared__ int s_red[32];

    const int s    = blockIdx.x;
    const int dir  = blockIdx.y;           // 0: tgt=B, src=A&~B ; 1: tgt=A, src=B&~A
    const int tid  = threadIdx.x;
    const int lane = tid & 31;
    const int wrp  = tid >> 5;             // 0..31 -> rows 3w..3w+2

    const float* __restrict__ P = pred + s * HW;
    const float* __restrict__ T = targ + s * HW;

    // ---- Load this warp's 3 rows (both arrays), 18 coalesced scalar loads.
    float av[9], bv[9];
    #pragma unroll
    for (int rr = 0; rr < 3; rr++) {
        const int base = (wrp * 3 + rr) * WD + lane;
        #pragma unroll
        for (int c = 0; c < 3; c++) {
            av[rr * 3 + c] = P[base + 32 * c];
            bv[rr * 3 + c] = T[base + 32 * c];
        }
    }

    // ---- Target masks via 9 ballots; source bits per-lane (no ballot).
    unsigned srcbits = 0;            // bit rr*3+c: this lane's pixel is a source
    unsigned anyT = 0;
    int rd2own[9];
    const bool loHalf = (lane < 16);
    #pragma unroll
    for (int rr = 0; rr < 3; rr++) {
        unsigned tm[3];
        #pragma unroll
        for (int c = 0; c < 3; c++) {
            bool a = av[rr * 3 + c] > 0.5f;   // round(x)>0.5 <=> x>0.5 on [0,1)
            bool b = bv[rr * 3 + c] > 0.5f;
            bool tgt = dir ? a : b;
            bool src = dir ? (b && !a) : (a && !b);
            tm[c] = __ballot_sync(0xffffffffu, tgt);
            srcbits |= (unsigned)src << (rr * 3 + c);
        }
        anyT |= tm[0] | tm[1] | tm[2];
        const int i = wrp * 3 + rr;

        #pragma unroll
        for (int c = 0; c < 3; c++) {
            const int j = lane + 32 * c;
            const unsigned mprev = (c == 0) ? 0u : tm[c - 1];
            const unsigned mcur  = tm[c];
            const unsigned mnext = (c == 2) ? 0u : tm[c + 1];
            // 32-bit window: bit k <-> row position j-16+k
            unsigned w = loHalf ? __funnelshift_r(mprev, mcur, lane + 16)
                                : __funnelshift_r(mcur, mnext, lane - 16);
            unsigned x = w & 0x1FFFFu;     // positions j-16..j
            unsigned y = w >> 16;          // positions j..j+15
            int dl = __clz(x) - 15;        // placeholder 17 when x==0
            int dr = __ffs(y) - 1;         // placeholder -1 when y==0
            // Cold path: only when some lane's half-window is empty (P ~ 5e-4/warp)
            if (__any_sync(0xffffffffu, (x == 0u) | (y == 0u))) {
                if (x == 0u) dl = exact_dl(j, tm[0], tm[1], tm[2]);
                if (y == 0u) dr = exact_dr(j, tm[0], tm[1], tm[2]);
            }
            int v = min(dl, dr);
            int v2 = v * v;
            rd2own[rr * 3 + c] = v2;
            s_rd2[i * WD + j] = (unsigned short)v2;
        }
    }

    // Single barrier: global anyTgt OR + makes s_rd2 visible block-wide.
    const int anyTgt = __syncthreads_or((int)(anyT != 0));

    // ---- Column scan: branchless di=1 probe + early-exit loop from di=2.
    // Clamped boundary probes only duplicate candidates already covered => min safe.
    int best = -1;
    #pragma unroll
    for (int rr = 0; rr < 3; rr++) {
        const int i = wrp * 3 + rr;
        #pragma unroll
        for (int c = 0; c < 3; c++) {
            const int j = lane + 32 * c;
            int bst = ((srcbits >> (rr * 3 + c)) & 1u) ? rd2own[rr * 3 + c] : -1;
            const int loA = j;                 // row 0 clamp
            const int hiA = 95 * WD + j;       // row 95 clamp
            int au  = max(i * WD + j - WD, loA);
            int avd = min(i * WD + j + WD, hiA);
            bst = min(bst, 1 + (int)s_rd2[au]);
            bst = min(bst, 1 + (int)s_rd2[avd]);
            int di = 2, d2 = 4;
            while (d2 < bst) {                 // rare: only when local rd2 > 4
                au  = max(au - WD, loA);
                avd = min(avd + WD, hiA);
                bst = min(bst, d2 + (int)s_rd2[au]);
                bst = min(bst, d2 + (int)s_rd2[avd]);
                d2 += 2 * di + 1;
                di++;
            }
            best = max(best, bst);
        }
    }

    // ---- Block max-reduction (REDUX within warps)
    best = __reduce_max_sync(0xffffffffu, best);
    if (lane == 0) s_red[wrp] = best;
    __syncthreads();
    if (wrp == 0) {
        int m = __reduce_max_sync(0xffffffffu, s_red[lane]);
        if (lane == 0) {
            float r;
            if (m < 0)        r = 0.0f;                  // empty source set
            else if (!anyTgt) r = 1e9f;                  // src nonempty, tgt empty
            else              r = sqrtf((float)m) * (1.0f / 96.0f);
            g_dir[s * 2 + dir] = r;
            __threadfence();
            unsigned int t = atomicAdd(&g_count, 1);
            if (t == (unsigned int)(2 * n - 1)) {        // last block: finish + reset
                __threadfence();
                volatile float* gd = g_dir;
                float acc = 0.0f;
                for (int i = 0; i < n; i++)
                    acc += fmaxf(gd[2 * i], gd[2 * i + 1]);
                out[0] = acc / (float)n;
                g_count = 0;                             // self-reset for next replay
            }
        }
    }
}

extern "C" void kernel_launch(void* const* d_in, const int* in_sizes, int n_in,
                              void* d_out, int out_size) {
    const float* pred = (const float*)d_in[0];
    const float* targ = (const float*)d_in[1];
    float* out = (float*)d_out;
    int n = in_sizes[0] / HW;   // batch size (8)

    dim3 grid(n, 2);
    hausdorff_kernel<<<grid, NT>>>(pred, targ, out, n);
}